// round 16
// baseline (speedup 1.0000x reference)
#include <cuda_runtime.h>
#include <cuda_fp16.h>
#include <cstdint>

#define NN 100000
#define EE 1600000
#define GG 64
#define SCAN_B 391   // ceil(NN/256)

typedef unsigned long long u64;

// ---------------- scratch (static device memory; no allocs) ----------------
__device__ __align__(16) float  g_bufA[NN * 64];   // shortcut output
__device__ __align__(16) float  g_bufC[NN * 64];   // GEMM output (f32)
__device__ __align__(16) __half g_Zh[NN * 64];     // activated features (half)
__device__ __align__(16) __half g_Th[NN * 64];     // T1 (half)
__device__ __align__(16) __half g_Ph[NN * 64];     // P  (half)
__device__ int      g_cnt[NN];
__device__ int      g_scan[NN];
__device__ int      g_bsum[SCAN_B];
__device__ int      g_boff[SCAN_B];
__device__ int      g_done;
__device__ int      g_rowptr[NN + 1];
__device__ int      g_cursor[NN];
__device__ __align__(8) int2 g_csr[EE];   // (col, w-bits)
__device__ float    g_dis[NN];
__device__ double   g_sum[192];           // 3 layers x 64
__device__ double   g_sumsq[192];
__device__ unsigned g_pooled[GG * 64];

// ---------------- helpers ----------------
__device__ __forceinline__ unsigned enc_f32(float f) {
    unsigned u = __float_as_uint(f);
    return (u & 0x80000000u) ? ~u : (u | 0x80000000u);
}
__device__ __forceinline__ float dec_f32(unsigned u) {
    return (u & 0x80000000u) ? __uint_as_float(u & 0x7FFFFFFFu) : __uint_as_float(~u);
}
__device__ __forceinline__ u64 splat2(float f) {
    u64 r;
    unsigned u = __float_as_uint(f);
    asm("mov.b64 %0, {%1,%2};" : "=l"(r) : "r"(u), "r"(u));
    return r;
}
#define FMA2(acc, a, w) asm("fma.rn.f32x2 %0, %1, %2, %0;" : "+l"(acc) : "l"(a), "l"(w))
__device__ __forceinline__ void unpack2(u64 v, float& lo, float& hi) {
    unsigned a, b;
    asm("mov.b64 {%0,%1}, %2;" : "=r"(a), "=r"(b) : "l"(v));
    lo = __uint_as_float(a);
    hi = __uint_as_float(b);
}
__device__ __forceinline__ float lrelu(float v) { return v > 0.f ? v : 0.01f * v; }

// compute BN scale/shift for layer offset loff into smem (callers sync after)
__device__ __forceinline__ void bn_params(int tid, int loff,
                                          const float* __restrict__ ga,
                                          const float* __restrict__ be,
                                          float* s_sc, float* s_sh) {
    if (tid < 64) {
        double mu = g_sum[loff + tid] / (double)NN;
        double var = g_sumsq[loff + tid] / (double)NN - mu * mu;
        float sc = ga[tid] * (float)(1.0 / sqrt(var + 1e-5));
        s_sc[tid] = sc;
        s_sh[tid] = be[tid] - (float)mu * sc;
    }
}

// ---------------- degree histogram (int) ----------------
__global__ void k_deg(const int* __restrict__ ei) {
    int e = blockIdx.x * blockDim.x + threadIdx.x;
    if (e < EE) atomicAdd(&g_cnt[ei[e]], 1);
}

// ---------------- scan phase 1+2 fused (last block scans block sums) ----------------
__global__ void k_scan12() {
    __shared__ int sh[256];
    __shared__ int lastFlag;
    int t = threadIdx.x, i = blockIdx.x * 256 + t;
    int v = (i < NN) ? g_cnt[i] : 0;
    if (i < NN) g_dis[i] = v > 0 ? rsqrtf((float)v) : 0.0f;
    sh[t] = v;
    __syncthreads();
    for (int o = 1; o < 256; o <<= 1) {
        int x = (t >= o) ? sh[t - o] : 0;
        __syncthreads();
        sh[t] += x;
        __syncthreads();
    }
    if (i < NN) g_scan[i] = sh[t];
    if (t == 255) g_bsum[blockIdx.x] = sh[255];

    if (t == 0) {
        __threadfence();
        int old = atomicAdd(&g_done, 1);
        lastFlag = (old == SCAN_B - 1);
    }
    __syncthreads();
    if (lastFlag && t < 32) {
        __threadfence();
        int lane = t;
        int run = 0;
        for (int c = 0; c < SCAN_B; c += 32) {
            int idx = c + lane;
            int x = (idx < SCAN_B) ? g_bsum[idx] : 0;
            int s = x;
#pragma unroll
            for (int o = 1; o < 32; o <<= 1) {
                int y = __shfl_up_sync(0xffffffffu, s, o);
                if (lane >= o) s += y;
            }
            if (idx < SCAN_B) g_boff[idx] = run + s - x;  // exclusive
            run += __shfl_sync(0xffffffffu, s, 31);
        }
        if (lane == 0) g_done = 0;   // self-reset for graph replay
    }
}

__global__ void k_scan3() {
    int i = blockIdx.x * blockDim.x + threadIdx.x;
    if (i < NN) {
        int rp = g_scan[i] - g_cnt[i] + g_boff[i >> 8];
        g_rowptr[i] = rp;
        g_cursor[i] = rp;
    }
    if (i == 0) g_rowptr[NN] = EE;
}

// ---------------- CSR fill (norm folded in) ----------------
__global__ void k_fill(const int* __restrict__ ei) {
    int e = blockIdx.x * blockDim.x + threadIdx.x;
    if (e >= EE) return;
    int r = ei[e], c = ei[EE + e];
    float w = -g_dis[r] * g_dis[c];
    int pos = atomicAdd(&g_cursor[r], 1);
    g_csr[pos] = make_int2(c, __float_as_int(w));
}

// ---------------- f32 -> half convert, optional BN+lrelu ----------------
template <bool ACT>
__global__ __launch_bounds__(256) void k_cvt(const float2* __restrict__ src,
                                             __half2* __restrict__ dst,
                                             int loff,
                                             const float* __restrict__ ga,
                                             const float* __restrict__ be) {
    __shared__ float s_sc[64], s_sh[64];
    if (ACT) {
        bn_params(threadIdx.x, loff, ga, be, s_sc, s_sh);
        __syncthreads();
    }
    int i = blockIdx.x * blockDim.x + threadIdx.x;
    if (i >= NN * 32) return;
    int j2 = i & 31;
    float2 v = src[i];
    if (ACT) {
        float2 sc = ((const float2*)s_sc)[j2];
        float2 sh = ((const float2*)s_sh)[j2];
        v.x = lrelu(fmaf(v.x, sc.x, sh.x));
        v.y = lrelu(fmaf(v.y, sc.y, sh.y));
    }
    dst[i] = __float22half2_rn(v);
}

// ---------------- CSR SpMM (half src/dst): 2 rows per warp, 16 lanes x 4 cols ----------------
// gather = 1 x 128B line per edge. Accumulate f32, store half.
__global__ __launch_bounds__(256) void k_spmm_h(const uint2* __restrict__ src,
                                                uint2* __restrict__ dst) {
    int warp = threadIdx.x >> 5, lane = threadIdx.x & 31;
    int half_ = lane >> 4, hl = lane & 15;
    int row = blockIdx.x * 16 + warp * 2 + half_;
    bool valid = row < NN;
    int p  = valid ? g_rowptr[row] : 0;
    int pe = valid ? g_rowptr[row + 1] : 0;
    int len = pe - p;
    int mlen = max(len, __shfl_xor_sync(0xffffffffu, len, 16));

    float4 acc = make_float4(0.f, 0.f, 0.f, 0.f);
    for (int k = 0; k < mlen; k += 4) {
#pragma unroll
        for (int j = 0; j < 4; j++) {
            int kk = k + j;
            bool on = kk < len;
            int2 e = g_csr[min(p + kk, EE - 1)];
            if (on) {
                uint2 raw = src[(size_t)e.x * 16 + hl];
                float2 f0 = __half22float2(*reinterpret_cast<__half2*>(&raw.x));
                float2 f1 = __half22float2(*reinterpret_cast<__half2*>(&raw.y));
                float w = __int_as_float(e.y);
                acc.x += w * f0.x; acc.y += w * f0.y;
                acc.z += w * f1.x; acc.w += w * f1.y;
            }
        }
    }
    if (valid) {
        __half2 o0 = __float22half2_rn(make_float2(acc.x, acc.y));
        __half2 o1 = __float22half2_rn(make_float2(acc.z, acc.w));
        uint2 o;
        o.x = *reinterpret_cast<unsigned*>(&o0);
        o.y = *reinterpret_cast<unsigned*>(&o1);
        dst[(size_t)row * 16 + hl] = o;
    }
}

// ---------------- fused 3-matrix GEMM (f32x2) + BN-stats epilogue ----------------
// out = Z@(W0-W2) + T@W1 + P@(2*W2) + b. Z f32 (ACT: BN+lrelu on load); T,P half.
template <bool ACT>
__global__ __launch_bounds__(512, 1) void k_gemm3(const float* __restrict__ Z,
                                                  const uint2* __restrict__ Th,
                                                  const uint2* __restrict__ Ph,
                                                  const float* __restrict__ W,
                                                  const float* __restrict__ bias,
                                                  float* __restrict__ out, int loff,
                                                  const float* __restrict__ ga,
                                                  const float* __restrict__ be) {
    extern __shared__ float sm[];
    float* Wd = sm;                 // 192*128 floats (splatted pairs)
    float* At = sm + 192 * 128;     // 192*128 floats
    __shared__ float s_sc[64], s_sh[64];

    int tid = threadIdx.x;
    int base = blockIdx.x * 128;

    if (ACT) bn_params(tid, loff - 64, ga, be, s_sc, s_sh);   // previous layer's stats

    for (int i = tid; i < 192 * 64; i += 512) {
        int kk = i >> 6, c = i & 63;
        int m = kk >> 6, kr = kk & 63;
        float w = W[m * 4096 + kr * 64 + c];
        if (m == 0) w -= W[8192 + kr * 64 + c];
        else if (m == 2) w *= 2.0f;
        float2* d = (float2*)(Wd + (size_t)kk * 128 + c * 2);
        *d = make_float2(w, w);
    }
    if (ACT) __syncthreads();   // s_sc/s_sh ready before Z-tile load

    // Z tile (f32, optional ACT)
    for (int i = tid; i < 128 * 16; i += 512) {
        int row = i & 127, c4 = i >> 7;
        float4 v = make_float4(0.f, 0.f, 0.f, 0.f);
        if (base + row < NN) v = ((const float4*)Z)[(size_t)(base + row) * 16 + c4];
        if (ACT) {
            float4 sc4 = ((const float4*)s_sc)[c4];
            float4 sh4 = ((const float4*)s_sh)[c4];
            v.x = lrelu(fmaf(v.x, sc4.x, sh4.x));
            v.y = lrelu(fmaf(v.y, sc4.y, sh4.y));
            v.z = lrelu(fmaf(v.z, sc4.z, sh4.z));
            v.w = lrelu(fmaf(v.w, sc4.w, sh4.w));
        }
        float* d = At + (size_t)(c4 * 4) * 128 + row;
        d[0] = v.x; d[128] = v.y; d[256] = v.z; d[384] = v.w;
    }
    // T/P tiles (half)
    const uint2* hsrcs[2] = {Th, Ph};
#pragma unroll
    for (int m = 0; m < 2; m++) {
        const uint2* s = hsrcs[m];
        for (int i = tid; i < 128 * 16; i += 512) {
            int row = i & 127, c4 = i >> 7;
            float4 v = make_float4(0.f, 0.f, 0.f, 0.f);
            if (base + row < NN) {
                uint2 raw = s[(size_t)(base + row) * 16 + c4];
                float2 f0 = __half22float2(*reinterpret_cast<__half2*>(&raw.x));
                float2 f1 = __half22float2(*reinterpret_cast<__half2*>(&raw.y));
                v = make_float4(f0.x, f0.y, f1.x, f1.y);
            }
            float* d = At + (size_t)((m + 1) * 64 + c4 * 4) * 128 + row;
            d[0] = v.x; d[128] = v.y; d[256] = v.z; d[384] = v.w;
        }
    }
    __syncthreads();

    int warp = tid >> 5, lane = tid & 31;
    int j0 = warp * 4;

    u64 acc[2][4];
#pragma unroll
    for (int c = 0; c < 4; c++) {
        u64 b = splat2(bias[j0 + c]);
        acc[0][c] = b;
        acc[1][c] = b;
    }

    const char* wb = (const char*)(Wd + j0 * 2);     // + kk*512B
    const char* ab = (const char*)(At + 2 * lane);   // + kk*512B

#pragma unroll 4
    for (int kk = 0; kk < 192; kk++) {
        ulonglong2 w01 = *(const ulonglong2*)(wb + (size_t)kk * 512);
        ulonglong2 w23 = *(const ulonglong2*)(wb + (size_t)kk * 512 + 16);
        u64 a0 = *(const u64*)(ab + (size_t)kk * 512);
        u64 a1 = *(const u64*)(ab + (size_t)kk * 512 + 256);
        FMA2(acc[0][0], a0, w01.x); FMA2(acc[0][1], a0, w01.y);
        FMA2(acc[0][2], a0, w23.x); FMA2(acc[0][3], a0, w23.y);
        FMA2(acc[1][0], a1, w01.x); FMA2(acc[1][1], a1, w01.y);
        FMA2(acc[1][2], a1, w23.x); FMA2(acc[1][3], a1, w23.y);
    }

    float s[4] = {0.f, 0.f, 0.f, 0.f}, q[4] = {0.f, 0.f, 0.f, 0.f};
#pragma unroll
    for (int rp = 0; rp < 2; rp++) {
        int re = base + rp * 64 + 2 * lane;
        float lo[4], hi[4];
#pragma unroll
        for (int c = 0; c < 4; c++) unpack2(acc[rp][c], lo[c], hi[c]);
        if (re < NN) {
            *(float4*)(out + (size_t)re * 64 + j0) = make_float4(lo[0], lo[1], lo[2], lo[3]);
#pragma unroll
            for (int c = 0; c < 4; c++) { s[c] += lo[c]; q[c] += lo[c] * lo[c]; }
        }
        if (re + 1 < NN) {
            *(float4*)(out + (size_t)(re + 1) * 64 + j0) = make_float4(hi[0], hi[1], hi[2], hi[3]);
#pragma unroll
            for (int c = 0; c < 4; c++) { s[c] += hi[c]; q[c] += hi[c] * hi[c]; }
        }
    }
#pragma unroll
    for (int o = 16; o > 0; o >>= 1) {
#pragma unroll
        for (int c = 0; c < 4; c++) {
            s[c] += __shfl_down_sync(0xffffffffu, s[c], o);
            q[c] += __shfl_down_sync(0xffffffffu, q[c], o);
        }
    }
    if (lane == 0) {
#pragma unroll
        for (int c = 0; c < 4; c++) {
            atomicAdd(&g_sum[loff + j0 + c], (double)s[c]);
            atomicAdd(&g_sumsq[loff + j0 + c], (double)q[c]);
        }
    }
}

// ---------------- shortcut GEMM (f32x2): out = X @ Wsc + bsc ----------------
__global__ __launch_bounds__(512, 2) void k_sc2(const float* __restrict__ X,
                                                const float* __restrict__ W,
                                                const float* __restrict__ bias,
                                                float* __restrict__ out) {
    extern __shared__ float sm[];
    float* Wd = sm;               // 64*128
    float* At = sm + 64 * 128;    // 64*128

    int tid = threadIdx.x;
    int base = blockIdx.x * 128;

    for (int i = tid; i < 64 * 64; i += 512) {
        int kk = i >> 6, c = i & 63;
        float w = W[kk * 64 + c];
        float2* d = (float2*)(Wd + (size_t)kk * 128 + c * 2);
        *d = make_float2(w, w);
    }
    for (int i = tid; i < 128 * 16; i += 512) {
        int row = i & 127, c4 = i >> 7;
        float4 v = make_float4(0.f, 0.f, 0.f, 0.f);
        if (base + row < NN) v = ((const float4*)X)[(size_t)(base + row) * 16 + c4];
        float* d = At + (size_t)(c4 * 4) * 128 + row;
        d[0] = v.x; d[128] = v.y; d[256] = v.z; d[384] = v.w;
    }
    __syncthreads();

    int warp = tid >> 5, lane = tid & 31;
    int j0 = warp * 4;

    u64 acc[2][4];
#pragma unroll
    for (int c = 0; c < 4; c++) {
        u64 b = splat2(bias[j0 + c]);
        acc[0][c] = b;
        acc[1][c] = b;
    }
    const char* wb = (const char*)(Wd + j0 * 2);
    const char* ab = (const char*)(At + 2 * lane);
#pragma unroll 4
    for (int kk = 0; kk < 64; kk++) {
        ulonglong2 w01 = *(const ulonglong2*)(wb + (size_t)kk * 512);
        ulonglong2 w23 = *(const ulonglong2*)(wb + (size_t)kk * 512 + 16);
        u64 a0 = *(const u64*)(ab + (size_t)kk * 512);
        u64 a1 = *(const u64*)(ab + (size_t)kk * 512 + 256);
        FMA2(acc[0][0], a0, w01.x); FMA2(acc[0][1], a0, w01.y);
        FMA2(acc[0][2], a0, w23.x); FMA2(acc[0][3], a0, w23.y);
        FMA2(acc[1][0], a1, w01.x); FMA2(acc[1][1], a1, w01.y);
        FMA2(acc[1][2], a1, w23.x); FMA2(acc[1][3], a1, w23.y);
    }
#pragma unroll
    for (int rp = 0; rp < 2; rp++) {
        int re = base + rp * 64 + 2 * lane;
        float lo[4], hi[4];
#pragma unroll
        for (int c = 0; c < 4; c++) unpack2(acc[rp][c], lo[c], hi[c]);
        if (re < NN)
            *(float4*)(out + (size_t)re * 64 + j0) = make_float4(lo[0], lo[1], lo[2], lo[3]);
        if (re + 1 < NN)
            *(float4*)(out + (size_t)(re + 1) * 64 + j0) = make_float4(hi[0], hi[1], hi[2], hi[3]);
    }
}

// ---------------- layer 3: BN (inline) + lrelu + shortcut + segment-max pool ----------------
__global__ __launch_bounds__(256) void k_apply3(const float* __restrict__ pre,
                                                const float* __restrict__ sc,
                                                const int* __restrict__ batch,
                                                const float* __restrict__ ga,
                                                const float* __restrict__ be) {
    __shared__ float s_sc[64], s_sh[64];
    bn_params(threadIdx.x, 128, ga, be, s_sc, s_sh);
    __syncthreads();
    int j = threadIdx.x & 63, rg = threadIdx.x >> 6;
    int r0 = blockIdx.x * 32 + rg * 8;
    float scv = s_sc[j], shv = s_sh[j];
    float m = 0.f;
    int curb = -1;
    for (int k = 0; k < 8; k++) {
        int row = r0 + k;
        if (row >= NN) break;
        int b = batch[row];
        float v = lrelu(fmaf(pre[(size_t)row * 64 + j], scv, shv)) + sc[(size_t)row * 64 + j];
        if (b != curb) {
            if (curb >= 0) atomicMax(&g_pooled[curb * 64 + j], enc_f32(m));
            curb = b;
            m = v;
        } else {
            m = fmaxf(m, v);
        }
    }
    if (curb >= 0) atomicMax(&g_pooled[curb * 64 + j], enc_f32(m));
}

// ---------------- final: pooled @ w_lin + b_lin ----------------
__global__ void k_final(const float* __restrict__ wlin, const float* __restrict__ blin,
                        float* __restrict__ out) {
    int g = blockIdx.x, j = threadIdx.x;
    float v = dec_f32(g_pooled[g * 64 + j]) * wlin[j];
#pragma unroll
    for (int o = 16; o > 0; o >>= 1) v += __shfl_down_sync(0xffffffffu, v, o);
    __shared__ float s2[2];
    if ((j & 31) == 0) s2[j >> 5] = v;
    __syncthreads();
    if (j == 0) out[g] = s2[0] + s2[1] + blin[0];
}

// ---------------- launcher ----------------
extern "C" void kernel_launch(void* const* d_in, const int* in_sizes, int n_in,
                              void* d_out, int out_size) {
    const float* x     = (const float*)d_in[0];
    const int*   ei    = (const int*)d_in[1];
    const int*   batch = (const int*)d_in[2];
    const float* W[3]  = {(const float*)d_in[3], (const float*)d_in[5], (const float*)d_in[7]};
    const float* B[3]  = {(const float*)d_in[4], (const float*)d_in[6], (const float*)d_in[8]};
    const float* Ga[3] = {(const float*)d_in[9], (const float*)d_in[11], (const float*)d_in[13]};
    const float* Be[3] = {(const float*)d_in[10], (const float*)d_in[12], (const float*)d_in[14]};
    const float* wsc  = (const float*)d_in[15];
    const float* bsc  = (const float*)d_in[16];
    const float* wlin = (const float*)d_in[17];
    const float* blin = (const float*)d_in[18];
    float* out = (float*)d_out;

    const int GEMM_SMEM = 2 * 192 * 128 * 4;   // 196608 B
    const int SC_SMEM   = 2 * 64 * 128 * 4;    // 65536 B
    cudaFuncSetAttribute(k_gemm3<false>, cudaFuncAttributeMaxDynamicSharedMemorySize, GEMM_SMEM);
    cudaFuncSetAttribute(k_gemm3<true>,  cudaFuncAttributeMaxDynamicSharedMemorySize, GEMM_SMEM);
    cudaFuncSetAttribute(k_sc2, cudaFuncAttributeMaxDynamicSharedMemorySize, SC_SMEM);

    void *pA, *pC, *pZh, *pTh, *pPh, *pcnt, *psum, *psumsq, *ppool;
    cudaGetSymbolAddress(&pA, g_bufA);
    cudaGetSymbolAddress(&pC, g_bufC);
    cudaGetSymbolAddress(&pZh, g_Zh);
    cudaGetSymbolAddress(&pTh, g_Th);
    cudaGetSymbolAddress(&pPh, g_Ph);
    cudaGetSymbolAddress(&pcnt, g_cnt);
    cudaGetSymbolAddress(&psum, g_sum);
    cudaGetSymbolAddress(&psumsq, g_sumsq);
    cudaGetSymbolAddress(&ppool, g_pooled);

    float* bufA = (float*)pA;
    float* bufC = (float*)pC;
    __half2* Zh = (__half2*)pZh;
    uint2* Th = (uint2*)pTh;
    uint2* Ph = (uint2*)pPh;

    const int EB = (EE + 255) / 256;
    const int NB = (NN + 255) / 256;
    const int RB = (NN + 127) / 128;           // gemm3/sc2 grid
    const int SPB = (NN + 15) / 16;            // spmm grid (16 rows/block)
    const int AB = (NN + 31) / 32;             // apply3 grid
    const int CB = (NN * 32 + 255) / 256;      // convert grid (half2 elems)

    // ---- CSR build ----
    cudaMemsetAsync(pcnt, 0, NN * sizeof(int));
    k_deg<<<EB, 256>>>(ei);
    k_scan12<<<SCAN_B, 256>>>();
    k_scan3<<<NB, 256>>>();
    k_fill<<<EB, 256>>>(ei);

    cudaMemsetAsync(psum, 0, 192 * sizeof(double));
    cudaMemsetAsync(psumsq, 0, 192 * sizeof(double));

    // ---- layer 1 ----
    k_cvt<false><<<CB, 256>>>((const float2*)x, Zh, 0, nullptr, nullptr);
    k_spmm_h<<<SPB, 256>>>((const uint2*)Zh, Th);
    k_spmm_h<<<SPB, 256>>>((const uint2*)Th, Ph);
    k_gemm3<false><<<RB, 512, GEMM_SMEM>>>(x, Th, Ph, W[0], B[0], bufC, 0, nullptr, nullptr);

    // ---- layers 2,3 (BN+lrelu fused into convert / GEMM Z-load) ----
    for (int l = 1; l < 3; l++) {
        k_cvt<true><<<CB, 256>>>((const float2*)bufC, Zh, (l - 1) * 64, Ga[l - 1], Be[l - 1]);
        k_spmm_h<<<SPB, 256>>>((const uint2*)Zh, Th);
        k_spmm_h<<<SPB, 256>>>((const uint2*)Th, Ph);
        k_gemm3<true><<<RB, 512, GEMM_SMEM>>>(bufC, Th, Ph, W[l], B[l], bufC,
                                              l * 64, Ga[l - 1], Be[l - 1]);
    }

    k_sc2<<<RB, 512, SC_SMEM>>>(x, wsc, bsc, bufA);
    cudaMemsetAsync(ppool, 0, GG * 64 * sizeof(unsigned));
    k_apply3<<<AB, 256>>>(bufC, bufA, batch, Ga[2], Be[2]);
    k_final<<<GG, 64>>>(wlin, blin, out);
}